// round 1
// baseline (speedup 1.0000x reference)
#include <cuda_runtime.h>
#include <cstdint>

// Problem shapes
#define NG   1024          // segments
#define R0   8192          // theta0 rows
#define C0   4096          // theta0 cols / obs0 cols / mapping1 cols / obs2 len
#define R1   4096          // theta1 rows / p1 len
#define C1   2048          // theta1 cols
#define MR   512           // mapping1 rows / obs1 len

// Scratch (static device globals — no allocation)
__device__ float  d_s0[NG * C0];        // 16 MB segment sums
__device__ float  d_p1[R1];
__device__ float  d_p2[C0];
__device__ int    d_rowlist[R0];
__device__ int    d_startg[NG + 1];
__device__ double d_lossA, d_lossB, d_lossC;

// ---------------------------------------------------------------------------
__device__ __forceinline__ float block_reduce_sum(float v) {
    __shared__ float s[32];
    int lane = threadIdx.x & 31, w = threadIdx.x >> 5;
    #pragma unroll
    for (int o = 16; o; o >>= 1) v += __shfl_down_sync(0xffffffffu, v, o);
    if (!lane) s[w] = v;
    __syncthreads();
    int nw = (blockDim.x + 31) >> 5;
    v = (threadIdx.x < nw) ? s[threadIdx.x] : 0.f;
    if (w == 0) {
        #pragma unroll
        for (int o = 16; o; o >>= 1) v += __shfl_down_sync(0xffffffffu, v, o);
    }
    return v;  // valid in thread 0
}

// ---------------------------------------------------------------------------
// Kernel 1: build group row-lists from idx0 (handles int32 OR int64 storage),
// plus zero the accumulators / p2. Single block, 1024 threads.
__global__ void k_build(const int* __restrict__ idx_raw) {
    __shared__ int s_cnt[NG];
    __shared__ int s_scan[NG];
    __shared__ int s_flag;
    int t = threadIdx.x;
    if (t == 0) s_flag = 0;
    s_cnt[t] = 0;
    __syncthreads();

    // dtype detect: if stored as int64 (LE), hi-words of first 4096 entries are 0
    // (values < 1024). If int32, those words are random indices -> OR != 0.
    int orv = 0;
    for (int i = t; i < 4096; i += 1024) orv |= idx_raw[2 * i + 1];
    if (orv) atomicOr(&s_flag, 1);
    __syncthreads();
    const bool is64 = (s_flag == 0);

    // histogram
    for (int i = t; i < R0; i += 1024) {
        int g = is64 ? idx_raw[2 * i] : idx_raw[i];
        atomicAdd(&s_cnt[g], 1);
    }
    __syncthreads();

    // inclusive Hillis-Steele scan over 1024 counts
    int v = s_cnt[t];
    s_scan[t] = v;
    __syncthreads();
    for (int off = 1; off < NG; off <<= 1) {
        int add = (t >= off) ? s_scan[t - off] : 0;
        __syncthreads();
        s_scan[t] += add;
        __syncthreads();
    }
    int excl = s_scan[t] - v;
    d_startg[t] = excl;
    if (t == NG - 1) d_startg[NG] = s_scan[t];

    // scatter rows into group-contiguous order
    s_cnt[t] = excl;
    __syncthreads();
    for (int i = t; i < R0; i += 1024) {
        int g = is64 ? idx_raw[2 * i] : idx_raw[i];
        int pos = atomicAdd(&s_cnt[g], 1);
        d_rowlist[pos] = i;
    }

    // zero global accumulators
    for (int i = t; i < C0; i += 1024) d_p2[i] = 0.f;
    if (t == 0) { d_lossA = 0.0; d_lossB = 0.0; d_lossC = 0.0; }
}

// ---------------------------------------------------------------------------
// Kernel 2 (hot): segment-sum of exp(theta0) + fused loss_a.
// Grid: 1024 groups x 4 column tiles = 4096 blocks of 256 threads.
// Each thread owns 4 consecutive columns (one float4).
__global__ void k_seg(const float* __restrict__ theta0,
                      const float* __restrict__ obs0) {
    const int g    = blockIdx.x >> 2;
    const int tile = blockIdx.x & 3;
    const int col  = tile * 1024 + threadIdx.x * 4;
    const int s = d_startg[g], e = d_startg[g + 1];

    float4 acc = make_float4(0.f, 0.f, 0.f, 0.f);
    for (int r = s; r < e; r++) {
        const int row = d_rowlist[r];
        const float4 x = *reinterpret_cast<const float4*>(
            theta0 + (size_t)row * C0 + col);
        acc.x += __expf(x.x);
        acc.y += __expf(x.y);
        acc.z += __expf(x.z);
        acc.w += __expf(x.w);
    }
    const size_t oidx = (size_t)g * C0 + col;
    *reinterpret_cast<float4*>(d_s0 + oidx) = acc;

    const float4 o = *reinterpret_cast<const float4*>(obs0 + oidx);
    float dx = o.x - acc.x, dy = o.y - acc.y;
    float dz = o.z - acc.z, dw = o.w - acc.w;
    float l = dx * dx + dy * dy + dz * dz + dw * dw;
    l = block_reduce_sum(l);
    if (threadIdx.x == 0) atomicAdd(&d_lossA, (double)l);
}

// ---------------------------------------------------------------------------
// Kernel 3: p1[r] = sum_c exp(theta1[r,c]).  One warp per row.
__global__ void k_p1(const float* __restrict__ theta1) {
    const int warp = threadIdx.x >> 5, lane = threadIdx.x & 31;
    const int row  = blockIdx.x * 8 + warp;
    const float* base = theta1 + (size_t)row * C1;
    float acc = 0.f;
    for (int c = lane * 4; c < C1; c += 128) {
        float4 x = *reinterpret_cast<const float4*>(base + c);
        acc += __expf(x.x) + __expf(x.y) + __expf(x.z) + __expf(x.w);
    }
    #pragma unroll
    for (int o = 16; o; o >>= 1) acc += __shfl_down_sync(0xffffffffu, acc, o);
    if (!lane) d_p1[row] = acc;
}

// ---------------------------------------------------------------------------
// Kernel 4: m1 = mapping1 @ p1, loss_b. One block per output row.
__global__ void k_lossb(const float* __restrict__ mapping1,
                        const float* __restrict__ obs1) {
    const int j = blockIdx.x;
    const float* row = mapping1 + (size_t)j * C0;
    float acc = 0.f;
    for (int c = threadIdx.x * 4; c < C0; c += 1024) {
        float4 m = *reinterpret_cast<const float4*>(row + c);
        float4 p = *reinterpret_cast<const float4*>(d_p1 + c);
        acc += m.x * p.x + m.y * p.y + m.z * p.z + m.w * p.w;
    }
    acc = block_reduce_sum(acc);
    if (threadIdx.x == 0) {
        double d = (double)obs1[j] - (double)acc;
        atomicAdd(&d_lossB, d * d);
    }
}

// ---------------------------------------------------------------------------
// Kernel 5: p2[c] = sum_g s0[g,c] (exploits p2 == column-sum of segment sums).
// Grid: 32 group-tiles x 16 column-tiles = 512 blocks of 256 threads.
__global__ void k_p2() {
    const int gt = blockIdx.x >> 4, ct = blockIdx.x & 15;
    const int c  = ct * 256 + threadIdx.x;
    float sum = 0.f;
    const int g0 = gt * 32;
    #pragma unroll 4
    for (int g = g0; g < g0 + 32; g++) sum += d_s0[(size_t)g * C0 + c];
    atomicAdd(&d_p2[c], sum);
}

// ---------------------------------------------------------------------------
// Kernel 6: loss_c sum. Single block (needs complete p2).
__global__ void k_lossc(const float* __restrict__ obs2) {
    float acc = 0.f;
    for (int c = threadIdx.x; c < C0; c += 1024) {
        float d = obs2[c] - d_p2[c];
        acc += d * d;
    }
    acc = block_reduce_sum(acc);
    if (threadIdx.x == 0) d_lossC = (double)acc;
}

// ---------------------------------------------------------------------------
// Kernel 7: combine.
__global__ void k_final(float* __restrict__ out) {
    double la = d_lossA / ((double)NG * (double)C0);
    double lb = d_lossB / (double)MR;
    double lc = 0.5 * d_lossC / (double)C0;
    out[0] = (float)((la + lb + lc) / 3.0);
}

// ---------------------------------------------------------------------------
extern "C" void kernel_launch(void* const* d_in, const int* in_sizes, int n_in,
                              void* d_out, int out_size) {
    const float* theta0   = (const float*)d_in[0];
    const float* theta1   = (const float*)d_in[1];
    const float* obs0     = (const float*)d_in[2];
    const float* obs1     = (const float*)d_in[3];
    const float* obs2     = (const float*)d_in[4];
    const int*   idx_raw  = (const int*)d_in[5];   // int32 or int64 (detected)
    const float* mapping1 = (const float*)d_in[6];
    float* out = (float*)d_out;

    k_build<<<1, 1024>>>(idx_raw);
    k_seg  <<<NG * 4, 256>>>(theta0, obs0);
    k_p1   <<<R1 / 8, 256>>>(theta1);
    k_lossb<<<MR, 256>>>(mapping1, obs1);
    k_p2   <<<512, 256>>>();
    k_lossc<<<1, 1024>>>(obs2);
    k_final<<<1, 1>>>(out);
}

// round 2
// speedup vs baseline: 1.0399x; 1.0399x over previous
#include <cuda_runtime.h>
#include <cstdint>

// Problem shapes
#define NG   1024          // segments
#define R0   8192          // theta0 rows
#define C0   4096          // theta0 cols / obs0 cols / mapping1 cols / obs2 len
#define R1   4096          // theta1 rows / p1 len
#define C1   2048          // theta1 cols
#define MR   512           // mapping1 rows / obs1 len
#define GCHUNK 4           // groups per k_main block

// Scratch (static device globals — no allocation)
__device__ float  d_p1[R1];
__device__ float  d_p2[C0];
__device__ float  d_m1[MR];
__device__ int    d_rowlist[R0];
__device__ int    d_startg[NG + 1];
__device__ double d_lossA;

// ---------------------------------------------------------------------------
__device__ __forceinline__ float block_reduce_sum(float v) {
    __shared__ float s[32];
    int lane = threadIdx.x & 31, w = threadIdx.x >> 5;
    #pragma unroll
    for (int o = 16; o; o >>= 1) v += __shfl_down_sync(0xffffffffu, v, o);
    if (!lane) s[w] = v;
    __syncthreads();
    int nw = (blockDim.x + 31) >> 5;
    v = (threadIdx.x < nw) ? s[threadIdx.x] : 0.f;
    if (w == 0) {
        #pragma unroll
        for (int o = 16; o; o >>= 1) v += __shfl_down_sync(0xffffffffu, v, o);
    }
    return v;  // valid in thread 0
}

__device__ __forceinline__ double block_reduce_sum_d(double v, double* s) {
    int lane = threadIdx.x & 31, w = threadIdx.x >> 5;
    #pragma unroll
    for (int o = 16; o; o >>= 1) v += __shfl_down_sync(0xffffffffu, v, o);
    if (!lane) s[w] = v;
    __syncthreads();
    int nw = (blockDim.x + 31) >> 5;
    v = (threadIdx.x < nw) ? s[threadIdx.x] : 0.0;
    if (w == 0) {
        #pragma unroll
        for (int o = 16; o; o >>= 1) v += __shfl_down_sync(0xffffffffu, v, o);
    }
    return v;  // valid in thread 0
}

// ---------------------------------------------------------------------------
// Kernel 1: build group row-lists from idx0 (handles int32 OR int64 storage),
// zero all accumulators. Single block, 1024 threads.
__global__ void k_build(const int* __restrict__ idx_raw) {
    __shared__ int s_cnt[NG];
    __shared__ int s_scan[NG];
    __shared__ int s_flag;
    int t = threadIdx.x;
    if (t == 0) s_flag = 0;
    s_cnt[t] = 0;
    __syncthreads();

    // dtype detect: if stored as int64 (LE), hi-words of first 4096 entries are
    // all 0 (values < 1024). If int32, those words are other indices -> OR != 0.
    int orv = 0;
    for (int i = t; i < 4096; i += 1024) orv |= idx_raw[2 * i + 1];
    if (orv) atomicOr(&s_flag, 1);
    __syncthreads();
    const bool is64 = (s_flag == 0);

    // histogram
    for (int i = t; i < R0; i += 1024) {
        int g = is64 ? idx_raw[2 * i] : idx_raw[i];
        atomicAdd(&s_cnt[g], 1);
    }
    __syncthreads();

    // inclusive Hillis-Steele scan over 1024 counts
    int v = s_cnt[t];
    s_scan[t] = v;
    __syncthreads();
    for (int off = 1; off < NG; off <<= 1) {
        int add = (t >= off) ? s_scan[t - off] : 0;
        __syncthreads();
        s_scan[t] += add;
        __syncthreads();
    }
    int excl = s_scan[t] - v;
    d_startg[t] = excl;
    if (t == NG - 1) d_startg[NG] = s_scan[t];

    // scatter rows into group-contiguous order
    s_cnt[t] = excl;
    __syncthreads();
    for (int i = t; i < R0; i += 1024) {
        int g = is64 ? idx_raw[2 * i] : idx_raw[i];
        int pos = atomicAdd(&s_cnt[g], 1);
        d_rowlist[pos] = i;
    }

    // zero global accumulators
    for (int i = t; i < C0; i += 1024) d_p2[i] = 0.f;
    if (t < MR) d_m1[t] = 0.f;
    if (t == 0) d_lossA = 0.0;
}

// ---------------------------------------------------------------------------
// Kernel 2 (hot, fused): blocks [0,1024): segment-sum of exp(theta0) with
// fused loss_a and p2 accumulation (no s0 materialization).
// Blocks [1024,1536): p1[r] = sum_c exp(theta1[r,c]) (one warp per row).
__global__ void __launch_bounds__(256) k_main(
        const float* __restrict__ theta0,
        const float* __restrict__ obs0,
        const float* __restrict__ theta1) {
    if (blockIdx.x < NG) {
        // ---- segment-sum part: (group chunk, col tile) ----
        const int chunk = blockIdx.x >> 2;          // 0..255
        const int tile  = blockIdx.x & 3;           // 0..3
        const int col   = tile * 1024 + threadIdx.x * 4;

        float4 p2l  = make_float4(0.f, 0.f, 0.f, 0.f);
        float  lossl = 0.f;

        #pragma unroll 1
        for (int gi = 0; gi < GCHUNK; gi++) {
            const int g = chunk * GCHUNK + gi;
            const int s = d_startg[g], e = d_startg[g + 1];

            float4 acc = make_float4(0.f, 0.f, 0.f, 0.f);
            if (s < e) {
                // 2-deep software pipeline on the gathered row loads
                int row = d_rowlist[s];
                float4 x = *reinterpret_cast<const float4*>(
                    theta0 + (size_t)row * C0 + col);
                for (int r = s; r < e; r++) {
                    float4 nx = x;
                    if (r + 1 < e) {
                        int nrow = d_rowlist[r + 1];
                        nx = *reinterpret_cast<const float4*>(
                            theta0 + (size_t)nrow * C0 + col);
                    }
                    acc.x += __expf(x.x);
                    acc.y += __expf(x.y);
                    acc.z += __expf(x.z);
                    acc.w += __expf(x.w);
                    x = nx;
                }
            }
            p2l.x += acc.x; p2l.y += acc.y; p2l.z += acc.z; p2l.w += acc.w;

            const float4 o = *reinterpret_cast<const float4*>(
                obs0 + (size_t)g * C0 + col);
            float dx = o.x - acc.x, dy = o.y - acc.y;
            float dz = o.z - acc.z, dw = o.w - acc.w;
            lossl += dx * dx + dy * dy + dz * dz + dw * dw;
        }

        // p2 contribution: one atomic per owned column (256 adds/address total)
        atomicAdd(&d_p2[col + 0], p2l.x);
        atomicAdd(&d_p2[col + 1], p2l.y);
        atomicAdd(&d_p2[col + 2], p2l.z);
        atomicAdd(&d_p2[col + 3], p2l.w);

        float l = block_reduce_sum(lossl);
        if (threadIdx.x == 0) atomicAdd(&d_lossA, (double)l);
    } else {
        // ---- p1 part: one warp per theta1 row ----
        const int b    = blockIdx.x - NG;           // 0..511
        const int warp = threadIdx.x >> 5, lane = threadIdx.x & 31;
        const int row  = b * 8 + warp;
        const float* base = theta1 + (size_t)row * C1;
        float acc = 0.f;
        #pragma unroll 4
        for (int c = lane * 4; c < C1; c += 128) {
            float4 x = *reinterpret_cast<const float4*>(base + c);
            acc += __expf(x.x) + __expf(x.y) + __expf(x.z) + __expf(x.w);
        }
        #pragma unroll
        for (int o = 16; o; o >>= 1) acc += __shfl_down_sync(0xffffffffu, acc, o);
        if (!lane) d_p1[row] = acc;
    }
}

// ---------------------------------------------------------------------------
// Kernel 3: m1 = mapping1 @ p1 (GEMV), high-parallelism partial dots.
// Grid: 512 rows x 4 strips = 2048 blocks of 128 threads.
__global__ void __launch_bounds__(128) k_mv(const float* __restrict__ mapping1) {
    const int row   = blockIdx.x >> 2;
    const int strip = blockIdx.x & 3;
    const int c0    = strip * 1024;
    const float* mrow = mapping1 + (size_t)row * C0 + c0;
    const int t4 = threadIdx.x * 4;

    float4 ma = *reinterpret_cast<const float4*>(mrow + t4);
    float4 pa = *reinterpret_cast<const float4*>(d_p1 + c0 + t4);
    float4 mb = *reinterpret_cast<const float4*>(mrow + 512 + t4);
    float4 pb = *reinterpret_cast<const float4*>(d_p1 + c0 + 512 + t4);

    float acc = ma.x * pa.x + ma.y * pa.y + ma.z * pa.z + ma.w * pa.w
              + mb.x * pb.x + mb.y * pb.y + mb.z * pb.z + mb.w * pb.w;
    acc = block_reduce_sum(acc);
    if (threadIdx.x == 0) atomicAdd(&d_m1[row], acc);
}

// ---------------------------------------------------------------------------
// Kernel 4: loss_b + loss_c + final combine. Single block, 1024 threads.
__global__ void k_fin(const float* __restrict__ obs1,
                      const float* __restrict__ obs2,
                      float* __restrict__ out) {
    __shared__ double sred[32];
    const int t = threadIdx.x;

    double lb = 0.0;
    if (t < MR) {
        double d = (double)obs1[t] - (double)d_m1[t];
        lb = d * d;
    }
    lb = block_reduce_sum_d(lb, sred);
    __shared__ double s_lb;
    if (t == 0) s_lb = lb;
    __syncthreads();

    double lc = 0.0;
    for (int c = t; c < C0; c += 1024) {
        double d = (double)obs2[c] - (double)d_p2[c];
        lc += d * d;
    }
    lc = block_reduce_sum_d(lc, sred);

    if (t == 0) {
        double la = d_lossA / ((double)NG * (double)C0);
        double lbm = s_lb / (double)MR;
        double lcm = 0.5 * lc / (double)C0;
        out[0] = (float)((la + lbm + lcm) / 3.0);
    }
}

// ---------------------------------------------------------------------------
extern "C" void kernel_launch(void* const* d_in, const int* in_sizes, int n_in,
                              void* d_out, int out_size) {
    const float* theta0   = (const float*)d_in[0];
    const float* theta1   = (const float*)d_in[1];
    const float* obs0     = (const float*)d_in[2];
    const float* obs1     = (const float*)d_in[3];
    const float* obs2     = (const float*)d_in[4];
    const int*   idx_raw  = (const int*)d_in[5];   // int32 or int64 (detected)
    const float* mapping1 = (const float*)d_in[6];
    float* out = (float*)d_out;

    k_build<<<1, 1024>>>(idx_raw);
    k_main <<<NG + R1 / 8, 256>>>(theta0, obs0, theta1);
    k_mv   <<<MR * 4, 128>>>(mapping1);
    k_fin  <<<1, 1024>>>(obs1, obs2, out);
}

// round 3
// speedup vs baseline: 1.0742x; 1.0330x over previous
#include <cuda_runtime.h>
#include <cstdint>

// Problem shapes
#define NG   1024          // segments
#define R0   8192          // theta0 rows
#define C0   4096          // theta0 cols / obs0 cols / mapping1 cols / obs2 len
#define R1   4096          // theta1 rows / p1 len
#define C1   2048          // theta1 cols
#define MR   512           // mapping1 rows / obs1 len
#define GCHUNK 4           // groups per seg block

// Scratch (static device globals — zero-initialized at load; no allocation)
__device__ float  d_p1[R1];
__device__ float  d_p2[C0];
__device__ float  d_m1[MR];
__device__ int    d_cnt[NG];        // re-zeroed each run by k_scan
__device__ int    d_rowg[R0];
__device__ int    d_rowpos[R0];
__device__ int    d_rowlist[R0];
__device__ int    d_startg[NG + 1];
__device__ double d_lossA;

// ---------------------------------------------------------------------------
__device__ __forceinline__ float block_reduce_sum(float v) {
    __shared__ float s[32];
    int lane = threadIdx.x & 31, w = threadIdx.x >> 5;
    #pragma unroll
    for (int o = 16; o; o >>= 1) v += __shfl_down_sync(0xffffffffu, v, o);
    if (!lane) s[w] = v;
    __syncthreads();
    int nw = (blockDim.x + 31) >> 5;
    v = (threadIdx.x < nw) ? s[threadIdx.x] : 0.f;
    if (w == 0) {
        #pragma unroll
        for (int o = 16; o; o >>= 1) v += __shfl_down_sync(0xffffffffu, v, o);
    }
    return v;  // valid in thread 0
}

// ---------------------------------------------------------------------------
// Kernel 1: blocks [0,512): p1[r] = sum_c exp(theta1[r,c])  (warp per row)
//           blocks [512,544): count rows per group (global atomics) + zeroing.
__global__ void __launch_bounds__(256) k_pre(
        const float* __restrict__ theta1,
        const int*   __restrict__ idx_raw) {
    if (blockIdx.x < 512) {
        const int warp = threadIdx.x >> 5, lane = threadIdx.x & 31;
        const int row  = blockIdx.x * 8 + warp;
        const float* base = theta1 + (size_t)row * C1;
        float acc = 0.f;
        #pragma unroll 4
        for (int c = lane * 4; c < C1; c += 128) {
            float4 x = __ldcs(reinterpret_cast<const float4*>(base + c));
            acc += __expf(x.x) + __expf(x.y) + __expf(x.z) + __expf(x.w);
        }
        #pragma unroll
        for (int o = 16; o; o >>= 1) acc += __shfl_down_sync(0xffffffffu, acc, o);
        if (!lane) d_p1[row] = acc;
    } else {
        const int b = blockIdx.x - 512;          // 0..31
        const int t = threadIdx.x;

        // dtype detect over a fixed in-bounds window: hi-words of pairs
        // [0,512). int64 (values<1024) -> all zero; int32 -> group ids, P(all
        // zero) = (1/1024)^512 ~ 0.
        int w = idx_raw[2 * t + 1] | idx_raw[2 * (t + 256) + 1];
        int any = __syncthreads_or(w);
        const bool is64 = (any == 0);

        const int i = b * 256 + t;               // row index, covers all 8192
        const int g = is64 ? idx_raw[2 * i] : idx_raw[i];
        const int pos = atomicAdd(&d_cnt[g], 1);
        d_rowg[i]   = g;
        d_rowpos[i] = pos;

        // zero accumulators (each count block owns a 128-col slice of p2)
        if (t < 128) d_p2[b * 128 + t] = 0.f;
        if (b == 0) {
            if (t == 0) d_lossA = 0.0;
            d_m1[t] = 0.f;
            d_m1[t + 256] = 0.f;
        }
    }
}

// ---------------------------------------------------------------------------
// Kernel 2: single block — scan counts -> startg, scatter rowlist, reset cnt.
__global__ void __launch_bounds__(1024) k_scan() {
    __shared__ int s_scan[NG];
    __shared__ int s_base[NG];
    const int t = threadIdx.x;

    int v = d_cnt[t];
    d_cnt[t] = 0;                                // reset for next replay
    s_scan[t] = v;
    __syncthreads();
    for (int off = 1; off < NG; off <<= 1) {
        int add = (t >= off) ? s_scan[t - off] : 0;
        __syncthreads();
        s_scan[t] += add;
        __syncthreads();
    }
    const int excl = s_scan[t] - v;
    s_base[t] = excl;
    d_startg[t] = excl;
    if (t == NG - 1) d_startg[NG] = s_scan[t];
    __syncthreads();

    #pragma unroll
    for (int i = t; i < R0; i += 1024)
        d_rowlist[s_base[d_rowg[i]] + d_rowpos[i]] = i;
}

// ---------------------------------------------------------------------------
// Kernel 3 (hot): blocks [0,1024): segment-sum of exp(theta0) + fused loss_a
// + p2 accumulation. Blocks [1024,2048): m1 = mapping1 @ p1 (GEMV strips).
__global__ void __launch_bounds__(256) k_main(
        const float* __restrict__ theta0,
        const float* __restrict__ obs0,
        const float* __restrict__ mapping1) {
    if (blockIdx.x < NG) {
        const int chunk = blockIdx.x >> 2;       // 0..255
        const int tile  = blockIdx.x & 3;        // 0..3
        const int col   = tile * 1024 + threadIdx.x * 4;

        float4 p2l  = make_float4(0.f, 0.f, 0.f, 0.f);
        float  lossl = 0.f;

        #pragma unroll 1
        for (int gi = 0; gi < GCHUNK; gi++) {
            const int g = chunk * GCHUNK + gi;
            const int s = d_startg[g], e = d_startg[g + 1];

            float4 acc = make_float4(0.f, 0.f, 0.f, 0.f);
            if (s < e) {
                int row = d_rowlist[s];
                float4 x = __ldcs(reinterpret_cast<const float4*>(
                    theta0 + (size_t)row * C0 + col));
                for (int r = s; r < e; r++) {
                    float4 nx = x;
                    if (r + 1 < e) {
                        int nrow = d_rowlist[r + 1];
                        nx = __ldcs(reinterpret_cast<const float4*>(
                            theta0 + (size_t)nrow * C0 + col));
                    }
                    acc.x += __expf(x.x);
                    acc.y += __expf(x.y);
                    acc.z += __expf(x.z);
                    acc.w += __expf(x.w);
                    x = nx;
                }
            }
            p2l.x += acc.x; p2l.y += acc.y; p2l.z += acc.z; p2l.w += acc.w;

            const float4 o = *reinterpret_cast<const float4*>(
                obs0 + (size_t)g * C0 + col);
            float dx = o.x - acc.x, dy = o.y - acc.y;
            float dz = o.z - acc.z, dw = o.w - acc.w;
            lossl += dx * dx + dy * dy + dz * dz + dw * dw;
        }

        atomicAdd(&d_p2[col + 0], p2l.x);
        atomicAdd(&d_p2[col + 1], p2l.y);
        atomicAdd(&d_p2[col + 2], p2l.z);
        atomicAdd(&d_p2[col + 3], p2l.w);

        float l = block_reduce_sum(lossl);
        if (threadIdx.x == 0) atomicAdd(&d_lossA, (double)l);
    } else {
        // GEMV: 512 rows x 2 strips (2048 cols each), 2 float4 per thread
        const int b     = blockIdx.x - NG;       // 0..1023
        const int row   = b >> 1;
        const int strip = b & 1;
        const int c0    = strip * 2048;
        const float* mrow = mapping1 + (size_t)row * C0 + c0;
        const int t4 = threadIdx.x * 4;

        float4 ma = __ldcs(reinterpret_cast<const float4*>(mrow + t4));
        float4 pa = *reinterpret_cast<const float4*>(d_p1 + c0 + t4);
        float4 mb = __ldcs(reinterpret_cast<const float4*>(mrow + 1024 + t4));
        float4 pb = *reinterpret_cast<const float4*>(d_p1 + c0 + 1024 + t4);

        float acc = ma.x * pa.x + ma.y * pa.y + ma.z * pa.z + ma.w * pa.w
                  + mb.x * pb.x + mb.y * pb.y + mb.z * pb.z + mb.w * pb.w;
        acc = block_reduce_sum(acc);
        if (threadIdx.x == 0) atomicAdd(&d_m1[row], acc);
    }
}

// ---------------------------------------------------------------------------
// Kernel 4: loss_b + loss_c + combine. Single block, 512 threads, float.
__global__ void __launch_bounds__(512) k_fin(
        const float* __restrict__ obs1,
        const float* __restrict__ obs2,
        float* __restrict__ out) {
    const int t = threadIdx.x;

    float db = obs1[t] - d_m1[t];
    float lb = block_reduce_sum(db * db);
    __shared__ float s_lb;
    if (t == 0) s_lb = lb;
    __syncthreads();

    float lc = 0.f;
    #pragma unroll
    for (int c = t; c < C0; c += 512) {
        float d = obs2[c] - d_p2[c];
        lc += d * d;
    }
    lc = block_reduce_sum(lc);

    if (t == 0) {
        double la  = d_lossA / ((double)NG * (double)C0);
        double lbm = (double)s_lb / (double)MR;
        double lcm = 0.5 * (double)lc / (double)C0;
        out[0] = (float)((la + lbm + lcm) / 3.0);
    }
}

// ---------------------------------------------------------------------------
extern "C" void kernel_launch(void* const* d_in, const int* in_sizes, int n_in,
                              void* d_out, int out_size) {
    const float* theta0   = (const float*)d_in[0];
    const float* theta1   = (const float*)d_in[1];
    const float* obs0     = (const float*)d_in[2];
    const float* obs1     = (const float*)d_in[3];
    const float* obs2     = (const float*)d_in[4];
    const int*   idx_raw  = (const int*)d_in[5];   // int32 or int64 (detected)
    const float* mapping1 = (const float*)d_in[6];
    float* out = (float*)d_out;

    k_pre <<<544, 256>>>(theta1, idx_raw);
    k_scan<<<1, 1024>>>();
    k_main<<<2 * NG, 256>>>(theta0, obs0, mapping1);
    k_fin <<<1, 512>>>(obs1, obs2, out);
}